// round 11
// baseline (speedup 1.0000x reference)
#include <cuda_runtime.h>
#include <cuda_fp16.h>

// Problem constants
#define BATCH    8
#define S_BYTES  8192
#define NUM_EMB  384
#define BYTE_DIM 128
#define EMB_DIM  1024
#define NUM_TOK  2048
#define M_TOTAL  (BATCH * NUM_TOK)   // 16384
#define SCALE_F  11.313708498984761f // sqrt(128)

// fp16 copies of the tables + pooled intermediate
__device__ __half g_emb_h[NUM_EMB * BYTE_DIM];   // 96 KB  (L1-resident gather table)
__device__ __half g_w_h[EMB_DIM * BYTE_DIM];     // 256 KB [n][k]
__device__ __half g_pool_h[M_TOTAL * BYTE_DIM];  // 4 MB   [m][k]
__device__ int g_start[BATCH][NUM_TOK + 1];

// ---------------------------------------------------------------------------
// Kernel 1 (fused prep): blocks [0,256) segment bounds; [256,264) W fp32->fp16;
// [264,266) emb fp32->fp16.
// ---------------------------------------------------------------------------
#define SEG_BLOCKS 256

__global__ __launch_bounds__(256) void prep_kernel(const float* __restrict__ emb,
                                                   const float* __restrict__ W,
                                                   const int* __restrict__ bg) {
    const int tid = threadIdx.x;
    const int blk = blockIdx.x;

    if (blk < SEG_BLOCKS) {
        // ---- segment boundaries from sorted byte_groups ----
        const int b = blk >> 5;
        const int s = (blk & 31) * 256 + tid;
        const int* __restrict__ row = bg + (size_t)b * S_BYTES;
        const int g  = row[s];
        const int gp = (s == 0) ? -1 : row[s - 1];
        for (int t = gp + 1; t <= g; ++t) g_start[b][t] = s;
        if (s == S_BYTES - 1) {
            for (int t = g + 1; t <= NUM_TOK; ++t) g_start[b][t] = S_BYTES;
        }
        return;
    }

    if (blk < SEG_BLOCKS + 8) {
        // ---- W convert: 131072 floats = 32768 float4, 8 blocks x 256 x 16 ----
        const int base = (blk - SEG_BLOCKS) * 4096;  // float4 index base
        const float4* __restrict__ src = reinterpret_cast<const float4*>(W);
        uint2* __restrict__ dst = reinterpret_cast<uint2*>(g_w_h);
        #pragma unroll
        for (int i = 0; i < 16; ++i) {
            int idx = base + tid + i * 256;
            float4 v = src[idx];
            __half2 h0 = __floats2half2_rn(v.x, v.y);
            __half2 h1 = __floats2half2_rn(v.z, v.w);
            uint2 u;
            u.x = *reinterpret_cast<unsigned int*>(&h0);
            u.y = *reinterpret_cast<unsigned int*>(&h1);
            dst[idx] = u;
        }
        return;
    }

    // ---- emb convert: 49152 floats = 12288 float4, 2 blocks x 256 x 24 ----
    const int base = (blk - SEG_BLOCKS - 8) * 6144;
    const float4* __restrict__ src = reinterpret_cast<const float4*>(emb);
    uint2* __restrict__ dst = reinterpret_cast<uint2*>(g_emb_h);
    #pragma unroll
    for (int i = 0; i < 24; ++i) {
        int idx = base + tid + i * 256;
        float4 v = src[idx];
        __half2 h0 = __floats2half2_rn(v.x, v.y);
        __half2 h1 = __floats2half2_rn(v.z, v.w);
        uint2 u;
        u.x = *reinterpret_cast<unsigned int*>(&h0);
        u.y = *reinterpret_cast<unsigned int*>(&h1);
        dst[idx] = u;
    }
}

// ---------------------------------------------------------------------------
// Kernel 2: ragged mean pool in BYTE_DIM space. Warp-per-token; lane owns
// 4 channels (uint2 of the 256B fp16 emb row). Gather table is 96 KB fp16 ->
// L1-resident; negligible L2 traffic. fp32 accumulate, SCALE/cnt folded,
// fp16 store to g_pool_h (coalesced 256B rows).
// grid = (NUM_TOK/8, BATCH), block = 256 (8 warps = 8 tokens).
// ---------------------------------------------------------------------------
__global__ __launch_bounds__(256) void pool_kernel(const int* __restrict__ x) {
    const int b    = blockIdx.y;
    const int wid  = threadIdx.x >> 5;
    const int lane = threadIdx.x & 31;
    const int t    = blockIdx.x * 8 + wid;

    const int s0 = g_start[b][t];
    const int s1 = g_start[b][t + 1];
    const int cnt = s1 - s0;

    const int* __restrict__ xr = x + (size_t)b * S_BYTES;
    const uint2* __restrict__ eh = reinterpret_cast<const uint2*>(g_emb_h);  // 32/row

    float a0 = 0.f, a1 = 0.f, a2 = 0.f, a3 = 0.f;

    for (int base = s0; base < s1; base += 32) {
        const int nn = min(32, s1 - base);
        int myx = 0;
        if (base + lane < s1) myx = xr[base + lane];
        for (int i = 0; i < nn; ++i) {
            const int e = __shfl_sync(0xffffffffu, myx, i);
            uint2 u = eh[e * 32 + lane];             // L1-hit, 256B/warp
            float2 f0 = __half22float2(*reinterpret_cast<__half2*>(&u.x));
            float2 f1 = __half22float2(*reinterpret_cast<__half2*>(&u.y));
            a0 += f0.x; a1 += f0.y; a2 += f1.x; a3 += f1.y;
        }
    }

    const float sc = SCALE_F / (float)(cnt > 0 ? cnt : 1);
    __half2 h0 = __floats2half2_rn(a0 * sc, a1 * sc);
    __half2 h1 = __floats2half2_rn(a2 * sc, a3 * sc);
    uint2 o;
    o.x = *reinterpret_cast<unsigned int*>(&h0);
    o.y = *reinterpret_cast<unsigned int*>(&h1);
    reinterpret_cast<uint2*>(g_pool_h)[((size_t)b * NUM_TOK + t) * 32 + lane] = o;
}

// ---------------------------------------------------------------------------
// Kernel 3: tensor-core GEMM  out[m][n] = sum_k P[m][k] * W[n][k]
// M=16384, N=1024, K=128. fp16 inputs, fp32 accum via mma.sync.m16n8k16.
// Block tile 128x64, full K in smem (XOR-swizzled 16B chunks, conflict-free
// ldmatrix). 8 warps: 4 m-warps x 2 n-warps, warp tile 32x32.
// grid = (16 n-blocks, 128 m-blocks), 256 threads, 48 KB dynamic smem.
// ---------------------------------------------------------------------------
#define GM 128
#define GN 64

__device__ __forceinline__ unsigned smem_u32(const void* p) {
    return (unsigned)__cvta_generic_to_shared(p);
}

__global__ __launch_bounds__(256) void gemm_kernel(float* __restrict__ out) {
    extern __shared__ __align__(16) uint4 smem4[];
    uint4* At4 = smem4;              // 128 rows x 16 chunks (16B each)
    uint4* Bt4 = smem4 + GM * 16;    // 64 rows x 16 chunks

    const int tid = threadIdx.x;
    const int bn  = blockIdx.x;      // 0..15
    const int bm  = blockIdx.y;      // 0..127

    const uint4* __restrict__ Pg = reinterpret_cast<const uint4*>(g_pool_h);
    const uint4* __restrict__ Wg = reinterpret_cast<const uint4*>(g_w_h);

    // Cooperative swizzled tile loads (row = 16 chunks of 16B; phys = c^(r&7)).
    #pragma unroll
    for (int i = 0; i < 8; ++i) {
        int lin = tid + i * 256;
        int r = lin >> 4, c = lin & 15;
        At4[r * 16 + (c ^ (r & 7))] = Pg[((size_t)(bm * GM + r)) * 16 + c];
    }
    #pragma unroll
    for (int i = 0; i < 4; ++i) {
        int lin = tid + i * 256;
        int r = lin >> 4, c = lin & 15;
        Bt4[r * 16 + (c ^ (r & 7))] = Wg[((size_t)(bn * GN + r)) * 16 + c];
    }
    __syncthreads();

    const int wid  = tid >> 5;
    const int lane = tid & 31;
    const int wm   = wid & 3;        // 0..3 -> m offset wm*32
    const int wn   = wid >> 2;       // 0..1 -> n offset wn*32

    const unsigned a_base = smem_u32(At4);
    const unsigned b_base = smem_u32(Bt4);

    const int lr = lane & 15;        // row within 16
    const int lc = lane >> 4;        // which 8-half chunk (k lo/hi)

    float acc[2][4][4];
    #pragma unroll
    for (int mt = 0; mt < 2; ++mt)
        #pragma unroll
        for (int nt = 0; nt < 4; ++nt)
            #pragma unroll
            for (int j = 0; j < 4; ++j) acc[mt][nt][j] = 0.f;

    #pragma unroll
    for (int ks = 0; ks < 8; ++ks) {        // k16 steps
        unsigned a[2][4], bf[2][4];
        #pragma unroll
        for (int mt = 0; mt < 2; ++mt) {
            int r = wm * 32 + mt * 16 + lr;
            int c = ks * 2 + lc;
            unsigned addr = a_base + (unsigned)((r * 16 + (c ^ (r & 7))) * 16);
            asm volatile("ldmatrix.sync.aligned.m8n8.x4.shared.b16 {%0,%1,%2,%3}, [%4];"
                         : "=r"(a[mt][0]), "=r"(a[mt][1]), "=r"(a[mt][2]), "=r"(a[mt][3])
                         : "r"(addr));
        }
        #pragma unroll
        for (int pr = 0; pr < 2; ++pr) {    // each covers 2 n8 tiles
            int r = wn * 32 + pr * 16 + lr;
            int c = ks * 2 + lc;
            unsigned addr = b_base + (unsigned)((r * 16 + (c ^ (r & 7))) * 16);
            asm volatile("ldmatrix.sync.aligned.m8n8.x4.shared.b16 {%0,%1,%2,%3}, [%4];"
                         : "=r"(bf[pr][0]), "=r"(bf[pr][1]), "=r"(bf[pr][2]), "=r"(bf[pr][3])
                         : "r"(addr));
        }
        #pragma unroll
        for (int mt = 0; mt < 2; ++mt) {
            #pragma unroll
            for (int nt = 0; nt < 4; ++nt) {
                const int pr = nt >> 1, od = nt & 1;
                asm volatile(
                    "mma.sync.aligned.m16n8k16.row.col.f32.f16.f16.f32 "
                    "{%0,%1,%2,%3}, {%4,%5,%6,%7}, {%8,%9}, {%0,%1,%2,%3};"
                    : "+f"(acc[mt][nt][0]), "+f"(acc[mt][nt][1]),
                      "+f"(acc[mt][nt][2]), "+f"(acc[mt][nt][3])
                    : "r"(a[mt][0]), "r"(a[mt][1]), "r"(a[mt][2]), "r"(a[mt][3]),
                      "r"(bf[pr][od]), "r"(bf[pr][2 + od]));
            }
        }
    }

    // Epilogue: fragment (c0,c1) at (row, col), (c2,c3) at (row+8, col).
    const int er = lane >> 2;
    const int ec = (lane & 3) * 2;
    #pragma unroll
    for (int mt = 0; mt < 2; ++mt) {
        #pragma unroll
        for (int nt = 0; nt < 4; ++nt) {
            const int row = bm * GM + wm * 32 + mt * 16 + er;
            const int col = bn * GN + wn * 32 + nt * 8 + ec;
            *reinterpret_cast<float2*>(out + (size_t)row * EMB_DIM + col) =
                make_float2(acc[mt][nt][0], acc[mt][nt][1]);
            *reinterpret_cast<float2*>(out + (size_t)(row + 8) * EMB_DIM + col) =
                make_float2(acc[mt][nt][2], acc[mt][nt][3]);
        }
    }
}

// ---------------------------------------------------------------------------
// Launch
// ---------------------------------------------------------------------------
extern "C" void kernel_launch(void* const* d_in, const int* in_sizes, int n_in,
                              void* d_out, int out_size) {
    const int*   x    = (const int*)  d_in[0];  // [B, S_BYTES] int32
    const int*   bg   = (const int*)  d_in[1];  // [B, S_BYTES] int32 (sorted per row)
    const float* emb  = (const float*)d_in[2];  // [NUM_EMB, BYTE_DIM] fp32
    const float* wout = (const float*)d_in[3];  // [EMB_DIM, BYTE_DIM] fp32
    float* out = (float*)d_out;                 // [B, NUM_TOK, EMB_DIM] fp32

    (void)in_sizes; (void)n_in; (void)out_size;

    const int smem_bytes = (GM * 16 + GN * 16) * 16;  // 49152
    static bool attr_set = false;
    if (!attr_set) {
        cudaFuncSetAttribute(gemm_kernel,
                             cudaFuncAttributeMaxDynamicSharedMemorySize, smem_bytes);
        attr_set = true;
    }

    prep_kernel<<<SEG_BLOCKS + 10, 256>>>(emb, wout, bg);

    dim3 pgrid(NUM_TOK / 8, BATCH);            // (256, 8)
    pool_kernel<<<pgrid, 256>>>(x);

    dim3 ggrid(EMB_DIM / GN, M_TOTAL / GM);    // (16, 128)
    gemm_kernel<<<ggrid, 256, smem_bytes>>>(out);
}

// round 12
// speedup vs baseline: 1.1333x; 1.1333x over previous
#include <cuda_runtime.h>
#include <cuda_fp16.h>

// Problem constants
#define BATCH    8
#define S_BYTES  8192
#define NUM_EMB  384
#define BYTE_DIM 128
#define EMB_DIM  1024
#define NUM_TOK  2048
#define M_TOTAL  (BATCH * NUM_TOK)   // 16384
#define SCALE_F  11.313708498984761f // sqrt(128)

// fp16 copies of the tables + pooled intermediate
__device__ __half g_emb_h[NUM_EMB * BYTE_DIM];   // 96 KB  (L1-resident gather table)
__device__ __half g_w_h[EMB_DIM * BYTE_DIM];     // 256 KB [n][k]
__device__ __half g_pool_h[M_TOTAL * BYTE_DIM];  // 4 MB   [m][k]
__device__ int g_start[BATCH][NUM_TOK + 1];

// ---------------------------------------------------------------------------
// Kernel 1 (fused prep): blocks [0,256) segment bounds; [256,384) W convert
// (1 float4 per thread); [384,432) emb convert (1 float4 per thread).
// ---------------------------------------------------------------------------
#define SEG_BLOCKS 256
#define WCV_BLOCKS 128   // 128*256 = 32768 float4 = 131072 floats
#define ECV_BLOCKS 48    // 48*256  = 12288 float4 = 49152 floats

__global__ __launch_bounds__(256) void prep_kernel(const float* __restrict__ emb,
                                                   const float* __restrict__ W,
                                                   const int* __restrict__ bg) {
    const int tid = threadIdx.x;
    const int blk = blockIdx.x;

    if (blk < SEG_BLOCKS) {
        // ---- segment boundaries from sorted byte_groups ----
        const int b = blk >> 5;
        const int s = (blk & 31) * 256 + tid;
        const int* __restrict__ row = bg + (size_t)b * S_BYTES;
        const int g  = row[s];
        const int gp = (s == 0) ? -1 : row[s - 1];
        for (int t = gp + 1; t <= g; ++t) g_start[b][t] = s;
        if (s == S_BYTES - 1) {
            for (int t = g + 1; t <= NUM_TOK; ++t) g_start[b][t] = S_BYTES;
        }
        return;
    }

    const float4* src;
    uint2* dst;
    int idx;
    if (blk < SEG_BLOCKS + WCV_BLOCKS) {
        idx = (blk - SEG_BLOCKS) * 256 + tid;
        src = reinterpret_cast<const float4*>(W);
        dst = reinterpret_cast<uint2*>(g_w_h);
    } else {
        idx = (blk - SEG_BLOCKS - WCV_BLOCKS) * 256 + tid;
        src = reinterpret_cast<const float4*>(emb);
        dst = reinterpret_cast<uint2*>(g_emb_h);
    }
    float4 v = src[idx];
    __half2 h0 = __floats2half2_rn(v.x, v.y);
    __half2 h1 = __floats2half2_rn(v.z, v.w);
    uint2 u;
    u.x = *reinterpret_cast<unsigned int*>(&h0);
    u.y = *reinterpret_cast<unsigned int*>(&h1);
    dst[idx] = u;
}

// ---------------------------------------------------------------------------
// Kernel 2: ragged mean pool in BYTE_DIM space (unchanged; passed round 11).
// Warp-per-token; lane owns 4 channels. 96 KB fp16 table -> L1-resident.
// fp32 accumulate, SCALE/cnt folded, fp16 store (coalesced 256B rows).
// ---------------------------------------------------------------------------
__global__ __launch_bounds__(256) void pool_kernel(const int* __restrict__ x) {
    const int b    = blockIdx.y;
    const int wid  = threadIdx.x >> 5;
    const int lane = threadIdx.x & 31;
    const int t    = blockIdx.x * 8 + wid;

    const int s0 = g_start[b][t];
    const int s1 = g_start[b][t + 1];
    const int cnt = s1 - s0;

    const int* __restrict__ xr = x + (size_t)b * S_BYTES;
    const uint2* __restrict__ eh = reinterpret_cast<const uint2*>(g_emb_h);  // 32/row

    float a0 = 0.f, a1 = 0.f, a2 = 0.f, a3 = 0.f;

    for (int base = s0; base < s1; base += 32) {
        const int nn = min(32, s1 - base);
        int myx = 0;
        if (base + lane < s1) myx = xr[base + lane];
        for (int i = 0; i < nn; ++i) {
            const int e = __shfl_sync(0xffffffffu, myx, i);
            uint2 u = eh[e * 32 + lane];             // L1-hit, 256B/warp
            float2 f0 = __half22float2(*reinterpret_cast<__half2*>(&u.x));
            float2 f1 = __half22float2(*reinterpret_cast<__half2*>(&u.y));
            a0 += f0.x; a1 += f0.y; a2 += f1.x; a3 += f1.y;
        }
    }

    const float sc = SCALE_F / (float)(cnt > 0 ? cnt : 1);
    __half2 h0 = __floats2half2_rn(a0 * sc, a1 * sc);
    __half2 h1 = __floats2half2_rn(a2 * sc, a3 * sc);
    uint2 o;
    o.x = *reinterpret_cast<unsigned int*>(&h0);
    o.y = *reinterpret_cast<unsigned int*>(&h1);
    reinterpret_cast<uint2*>(g_pool_h)[((size_t)b * NUM_TOK + t) * 32 + lane] = o;
}

// ---------------------------------------------------------------------------
// Kernel 3: tensor-core GEMM  out[m][n] = sum_k P[m][k] * W[n][k]
// M=16384, N=1024, K=128. fp16 in, fp32 accum, mma.sync.m16n8k16.
// Block tile 128x128, full K in smem (XOR-swizzled 16B chunks), 64 KB smem.
// 8 warps: 4 m-warps x 2 n-warps, warp tile 32x128. 2 CTAs/SM forced.
// grid = (8 n-blocks, 128 m-blocks), 256 threads.
// ---------------------------------------------------------------------------
#define GM 128
#define GN 128

__device__ __forceinline__ unsigned smem_u32(const void* p) {
    return (unsigned)__cvta_generic_to_shared(p);
}

__global__ __launch_bounds__(256, 2) void gemm_kernel(float* __restrict__ out) {
    extern __shared__ __align__(16) uint4 smem4[];
    uint4* At4 = smem4;              // 128 rows x 16 chunks (16B each)
    uint4* Bt4 = smem4 + GM * 16;    // 128 rows x 16 chunks

    const int tid = threadIdx.x;
    const int bn  = blockIdx.x;      // 0..7
    const int bm  = blockIdx.y;      // 0..127

    const uint4* __restrict__ Pg = reinterpret_cast<const uint4*>(g_pool_h);
    const uint4* __restrict__ Wg = reinterpret_cast<const uint4*>(g_w_h);

    // Cooperative swizzled tile loads (row = 16 chunks of 16B; phys = c^(r&7)).
    #pragma unroll
    for (int i = 0; i < 8; ++i) {
        int lin = tid + i * 256;
        int r = lin >> 4, c = lin & 15;
        At4[r * 16 + (c ^ (r & 7))] = Pg[((size_t)(bm * GM + r)) * 16 + c];
    }
    #pragma unroll
    for (int i = 0; i < 8; ++i) {
        int lin = tid + i * 256;
        int r = lin >> 4, c = lin & 15;
        Bt4[r * 16 + (c ^ (r & 7))] = Wg[((size_t)(bn * GN + r)) * 16 + c];
    }
    __syncthreads();

    const int wid  = tid >> 5;
    const int lane = tid & 31;
    const int wm   = wid & 3;        // m offset wm*32
    const int wn   = wid >> 2;       // n offset wn*64

    const unsigned a_base = smem_u32(At4);
    const unsigned b_base = smem_u32(Bt4);

    const int lr = lane & 15;        // row within 16
    const int lc = lane >> 4;        // which 8-half chunk (k lo/hi)

    // Hoisted per-fragment row bases and swizzle keys.
    unsigned a_row[2]; int a_sw[2];
    #pragma unroll
    for (int mt = 0; mt < 2; ++mt) {
        int r = wm * 32 + mt * 16 + lr;
        a_row[mt] = a_base + (unsigned)(r * 256);
        a_sw[mt]  = r & 7;
    }
    unsigned b_row[4]; int b_sw[4];
    #pragma unroll
    for (int pr = 0; pr < 4; ++pr) {
        int r = wn * 64 + pr * 16 + lr;
        b_row[pr] = b_base + (unsigned)(r * 256);
        b_sw[pr]  = r & 7;
    }

    float acc[2][8][4];
    #pragma unroll
    for (int mt = 0; mt < 2; ++mt)
        #pragma unroll
        for (int nt = 0; nt < 8; ++nt)
            #pragma unroll
            for (int j = 0; j < 4; ++j) acc[mt][nt][j] = 0.f;

    #pragma unroll
    for (int ks = 0; ks < 8; ++ks) {        // k16 steps
        const int c = ks * 2 + lc;
        unsigned a[2][4], bf[4][4];
        #pragma unroll
        for (int mt = 0; mt < 2; ++mt) {
            unsigned addr = a_row[mt] + (unsigned)((c ^ a_sw[mt]) << 4);
            asm volatile("ldmatrix.sync.aligned.m8n8.x4.shared.b16 {%0,%1,%2,%3}, [%4];"
                         : "=r"(a[mt][0]), "=r"(a[mt][1]), "=r"(a[mt][2]), "=r"(a[mt][3])
                         : "r"(addr));
        }
        #pragma unroll
        for (int pr = 0; pr < 4; ++pr) {    // each covers 2 n8 tiles
            unsigned addr = b_row[pr] + (unsigned)((c ^ b_sw[pr]) << 4);
            asm volatile("ldmatrix.sync.aligned.m8n8.x4.shared.b16 {%0,%1,%2,%3}, [%4];"
                         : "=r"(bf[pr][0]), "=r"(bf[pr][1]), "=r"(bf[pr][2]), "=r"(bf[pr][3])
                         : "r"(addr));
        }
        #pragma unroll
        for (int mt = 0; mt < 2; ++mt) {
            #pragma unroll
            for (int nt = 0; nt < 8; ++nt) {
                const int pr = nt >> 1, od = nt & 1;
                asm volatile(
                    "mma.sync.aligned.m16n8k16.row.col.f32.f16.f16.f32 "
                    "{%0,%1,%2,%3}, {%4,%5,%6,%7}, {%8,%9}, {%0,%1,%2,%3};"
                    : "+f"(acc[mt][nt][0]), "+f"(acc[mt][nt][1]),
                      "+f"(acc[mt][nt][2]), "+f"(acc[mt][nt][3])
                    : "r"(a[mt][0]), "r"(a[mt][1]), "r"(a[mt][2]), "r"(a[mt][3]),
                      "r"(bf[pr][od]), "r"(bf[pr][2 + od]));
            }
        }
    }

    // Epilogue: fragment (c0,c1) at (row, col), (c2,c3) at (row+8, col).
    const int er = lane >> 2;
    const int ec = (lane & 3) * 2;
    #pragma unroll
    for (int mt = 0; mt < 2; ++mt) {
        #pragma unroll
        for (int nt = 0; nt < 8; ++nt) {
            const int row = bm * GM + wm * 32 + mt * 16 + er;
            const int col = bn * GN + wn * 64 + nt * 8 + ec;
            *reinterpret_cast<float2*>(out + (size_t)row * EMB_DIM + col) =
                make_float2(acc[mt][nt][0], acc[mt][nt][1]);
            *reinterpret_cast<float2*>(out + (size_t)(row + 8) * EMB_DIM + col) =
                make_float2(acc[mt][nt][2], acc[mt][nt][3]);
        }
    }
}

// ---------------------------------------------------------------------------
// Launch
// ---------------------------------------------------------------------------
extern "C" void kernel_launch(void* const* d_in, const int* in_sizes, int n_in,
                              void* d_out, int out_size) {
    const int*   x    = (const int*)  d_in[0];  // [B, S_BYTES] int32
    const int*   bg   = (const int*)  d_in[1];  // [B, S_BYTES] int32 (sorted per row)
    const float* emb  = (const float*)d_in[2];  // [NUM_EMB, BYTE_DIM] fp32
    const float* wout = (const float*)d_in[3];  // [EMB_DIM, BYTE_DIM] fp32
    float* out = (float*)d_out;                 // [B, NUM_TOK, EMB_DIM] fp32

    (void)in_sizes; (void)n_in; (void)out_size;

    const int smem_bytes = (GM * 16 + GN * 16) * 16;  // 65536
    static bool attr_set = false;
    if (!attr_set) {
        cudaFuncSetAttribute(gemm_kernel,
                             cudaFuncAttributeMaxDynamicSharedMemorySize, smem_bytes);
        attr_set = true;
    }

    prep_kernel<<<SEG_BLOCKS + WCV_BLOCKS + ECV_BLOCKS, 256>>>(emb, wout, bg);

    dim3 pgrid(NUM_TOK / 8, BATCH);            // (256, 8)
    pool_kernel<<<pgrid, 256>>>(x);

    dim3 ggrid(EMB_DIM / GN, M_TOTAL / GM);    // (8, 128)
    gemm_kernel<<<ggrid, 256, smem_bytes>>>(out);
}

// round 13
// speedup vs baseline: 1.9070x; 1.6827x over previous
#include <cuda_runtime.h>
#include <cuda_fp16.h>

// Problem constants
#define BATCH    8
#define S_BYTES  8192
#define NUM_EMB  384
#define BYTE_DIM 128
#define EMB_DIM  1024
#define NUM_TOK  2048
#define SCALE_F  11.313708498984761f  // sqrt(128)

// proj = SCALE * emb @ W^T, stored fp16: [NUM_EMB, EMB_DIM] (768 KB, L2-resident)
__device__ __half g_proj_h[NUM_EMB * EMB_DIM];

// ---------------------------------------------------------------------------
// Kernel 1: tiny GEMM  proj[e][n] = SCALE * sum_k emb[e][k] * W[n][k]
// M=384, N=1024, K=128. 32x32 tiles (384 blocks), full K in smem, one sync.
// fp32 math, fp16 store.
// ---------------------------------------------------------------------------
#define BM 32
#define BN 32
#define SPITCH 33

__global__ __launch_bounds__(256) void proj_gemm_kernel(const float* __restrict__ emb,
                                                        const float* __restrict__ W) {
    __shared__ float As[BYTE_DIM][SPITCH];  // [k][m]
    __shared__ float Ws[BYTE_DIM][SPITCH];  // [k][n]

    const int tid = threadIdx.x;
    const int bn = blockIdx.x & 31;   // 0..31
    const int bm = blockIdx.x >> 5;   // 0..11
    const int tx = tid & 15;
    const int ty = tid >> 4;
    const int m0 = ty * 2;
    const int n0 = tx * 2;

    const float* __restrict__ A  = emb + (size_t)(bm * BM) * BYTE_DIM;
    const float* __restrict__ Wt = W   + (size_t)(bn * BN) * BYTE_DIM;

    #pragma unroll
    for (int i = 0; i < 16; ++i) {
        int f = tid + i * 256;
        int k = f & 127;
        int r = f >> 7;
        As[k][r] = A [(size_t)r * BYTE_DIM + k];
        Ws[k][r] = Wt[(size_t)r * BYTE_DIM + k];
    }
    __syncthreads();

    float acc[2][2] = {};
    #pragma unroll 8
    for (int k = 0; k < BYTE_DIM; ++k) {
        float a0 = As[k][m0], a1 = As[k][m0 + 1];
        float w0 = Ws[k][n0], w1 = Ws[k][n0 + 1];
        acc[0][0] = fmaf(a0, w0, acc[0][0]);
        acc[0][1] = fmaf(a0, w1, acc[0][1]);
        acc[1][0] = fmaf(a1, w0, acc[1][0]);
        acc[1][1] = fmaf(a1, w1, acc[1][1]);
    }

    #pragma unroll
    for (int i = 0; i < 2; ++i) {
        __half2 h = __floats2half2_rn(acc[i][0] * SCALE_F, acc[i][1] * SCALE_F);
        *reinterpret_cast<__half2*>(
            g_proj_h + (size_t)(bm * BM + m0 + i) * EMB_DIM + bn * BN + n0) = h;
    }
}

// ---------------------------------------------------------------------------
// Warp-cooperative lower_bound over a sorted row of S_BYTES ints.
// 32-ary search, 3 rounds (step 256 -> 8 -> 1). Out-of-range probes use
// sentinels: p < 0 acts as -inf (pred true), p >= S_BYTES as +inf (pred
// false). Returns first index i with row[i] >= v, in [0, S_BYTES].
// ---------------------------------------------------------------------------
__device__ __forceinline__ int warp_lower_bound(const int* __restrict__ row,
                                                int v, int lane) {
    // Round 1: probes 0, 256, ..., 7936 (always in range).
    bool pr = row[lane << 8] < v;
    int c1 = __popc(__ballot_sync(0xffffffffu, pr));
    int base = c1 << 8;

    // Round 2: probes base-255 + 8*lane  (max = base-7 <= 8185, min may be <0).
    int p2 = base - 255 + (lane << 3);
    pr = (p2 < 0) || (row[p2] < v);
    int c2 = __popc(__ballot_sync(0xffffffffu, pr));
    int L = base + (c2 << 3) - 262;

    // Round 3: probes L..L+7 (lanes 0..7), may underflow/overflow range.
    int p3 = L + lane;
    pr = (p3 < 0) || (p3 < S_BYTES && row[p3] < v);
    int c3 = __popc(__ballot_sync(0xffffffffu, pr) & 0xff);
    return L + c3;
}

// ---------------------------------------------------------------------------
// Kernel 2: ragged mean over fp16 proj rows, warp-per-token (round-6 champion
// body), with segment bounds computed INLINE by warp-cooperative search (no
// separate seg-bounds kernel, no g_start round-trip).
// grid = (NUM_TOK/8, BATCH), block = 256 (8 warps = 8 tokens).
// ---------------------------------------------------------------------------
__global__ __launch_bounds__(256) void pool_kernel(const int* __restrict__ x,
                                                   const int* __restrict__ bg,
                                                   float* __restrict__ out) {
    const int b    = blockIdx.y;
    const int wid  = threadIdx.x >> 5;
    const int lane = threadIdx.x & 31;
    const int t    = blockIdx.x * 8 + wid;

    const int* __restrict__ row = bg + (size_t)b * S_BYTES;
    const int s0 = warp_lower_bound(row, t, lane);
    const int s1 = warp_lower_bound(row, t + 1, lane);
    const int cnt = s1 - s0;

    const int* __restrict__ xr = x + (size_t)b * S_BYTES;
    const uint2* __restrict__ p = reinterpret_cast<const uint2*>(g_proj_h);  // 256/row

    float4 acc[8];
    #pragma unroll
    for (int j = 0; j < 8; ++j) acc[j] = make_float4(0.f, 0.f, 0.f, 0.f);

    for (int s = s0; s < s1; ++s) {
        const int e = xr[s];  // warp-broadcast load
        const uint2* __restrict__ pr = p + (size_t)e * (EMB_DIM / 4);
        #pragma unroll
        for (int j = 0; j < 8; ++j) {
            uint2 u = pr[lane + 32 * j];  // coalesced 256B wavefront, L2-hit
            __half2 h0 = *reinterpret_cast<__half2*>(&u.x);
            __half2 h1 = *reinterpret_cast<__half2*>(&u.y);
            float2 f0 = __half22float2(h0);
            float2 f1 = __half22float2(h1);
            acc[j].x += f0.x; acc[j].y += f0.y;
            acc[j].z += f1.x; acc[j].w += f1.y;
        }
    }

    const float inv = 1.0f / (float)(cnt > 0 ? cnt : 1);

    float4* __restrict__ o =
        reinterpret_cast<float4*>(out) + (((size_t)b * NUM_TOK) + t) * (EMB_DIM / 4);
    #pragma unroll
    for (int j = 0; j < 8; ++j) {
        float4 v = make_float4(acc[j].x * inv, acc[j].y * inv,
                               acc[j].z * inv, acc[j].w * inv);
        o[lane + 32 * j] = v;  // coalesced STG.128
    }
}

// ---------------------------------------------------------------------------
// Launch
// ---------------------------------------------------------------------------
extern "C" void kernel_launch(void* const* d_in, const int* in_sizes, int n_in,
                              void* d_out, int out_size) {
    const int*   x    = (const int*)  d_in[0];  // [B, S_BYTES] int32
    const int*   bg   = (const int*)  d_in[1];  // [B, S_BYTES] int32 (sorted per row)
    const float* emb  = (const float*)d_in[2];  // [NUM_EMB, BYTE_DIM] fp32
    const float* wout = (const float*)d_in[3];  // [EMB_DIM, BYTE_DIM] fp32
    float* out = (float*)d_out;                 // [B, NUM_TOK, EMB_DIM] fp32

    (void)in_sizes; (void)n_in; (void)out_size;

    proj_gemm_kernel<<<(EMB_DIM / BN) * (NUM_EMB / BM), 256>>>(emb, wout);  // 384 blocks

    dim3 pgrid(NUM_TOK / 8, BATCH);             // (256, 8) = 2048 blocks
    pool_kernel<<<pgrid, 256>>>(x, bg, out);
}